// round 2
// baseline (speedup 1.0000x reference)
#include <cuda_runtime.h>
#include <math.h>

#define BN_TOTAL 2048
#define NDESC 128
#define NB 256

// ---------------- device scratch (no allocations allowed) ----------------
__device__ float  g_d1[BN_TOTAL * NDESC];   // packed desc of my_feature
__device__ float  g_d2[BN_TOTAL * NDESC];   // packed desc of my_tf_feature
__device__ float2 g_p1[BN_TOTAL];           // pts1 = trunc(my_tf_kp)
__device__ float2 g_p2[BN_TOTAL];           // pts2 = trunc(rotated my_kp)
__device__ float4 g_L[BN_TOTAL];            // L[i] = p1h[i]^T F  (x,y,z used)

// ---------------- K0: repack descriptors for aligned float4 loads ----------
__global__ void k0_repack(const float* __restrict__ feat1,
                          const float* __restrict__ feat2) {
    int idx = blockIdx.x * blockDim.x + threadIdx.x;
    if (idx >= BN_TOTAL * NDESC) return;
    int i = idx >> 7, k = idx & 127;
    g_d1[idx] = feat1[(size_t)i * 130 + 2 + k];
    g_d2[idx] = feat2[(size_t)i * 130 + 2 + k];
}

// ---------------- serial Jacobi eigensolver (symmetric, double) -----------
__device__ void jacobi_sym(double* A, double* V, int n) {
    for (int i = 0; i < n; i++)
        for (int j = 0; j < n; j++)
            V[i * n + j] = (i == j) ? 1.0 : 0.0;
    // Frobenius^2 for relative convergence threshold
    double fro2 = 0.0;
    for (int i = 0; i < n * n; i++) fro2 += A[i] * A[i];
    double thresh = 1e-28 * fro2 + 1e-300;
    for (int sweep = 0; sweep < 30; sweep++) {
        double off = 0.0;
        for (int p = 0; p < n - 1; p++)
            for (int q = p + 1; q < n; q++)
                off += A[p * n + q] * A[p * n + q];
        if (off < thresh) break;
        for (int p = 0; p < n - 1; p++) {
            for (int q = p + 1; q < n; q++) {
                double apq = A[p * n + q];
                if (fabs(apq) < 1e-300) continue;
                double app = A[p * n + p], aqq = A[q * n + q];
                double theta = (aqq - app) / (2.0 * apq);
                double t = ((theta >= 0.0) ? 1.0 : -1.0) /
                           (fabs(theta) + sqrt(theta * theta + 1.0));
                double c = 1.0 / sqrt(t * t + 1.0);
                double s = t * c;
                // A <- J^T A J  (two-sided Givens)
                for (int k = 0; k < n; k++) {
                    double akp = A[k * n + p], akq = A[k * n + q];
                    A[k * n + p] = c * akp - s * akq;
                    A[k * n + q] = s * akp + c * akq;
                }
                for (int k = 0; k < n; k++) {
                    double apk = A[p * n + k], aqk = A[q * n + k];
                    A[p * n + k] = c * apk - s * aqk;
                    A[q * n + k] = s * apk + c * aqk;
                }
                for (int k = 0; k < n; k++) {
                    double vkp = V[k * n + p], vkq = V[k * n + q];
                    V[k * n + p] = c * vkp - s * vkq;
                    V[k * n + q] = s * vkp + c * vkq;
                }
            }
        }
    }
}

__device__ double block_reduce_sum(double v, double* sred) {
    int t = threadIdx.x;
    sred[t] = v;
    __syncthreads();
    for (int o = 128; o > 0; o >>= 1) {
        if (t < o) sred[t] += sred[t + o];
        __syncthreads();
    }
    double r = sred[0];
    __syncthreads();
    return r;
}

// ---------------- K1: pts, normalization, F (8-point), L rows --------------
__global__ void __launch_bounds__(256) k1_model(const float* __restrict__ theta,
                                                const float* __restrict__ feat1,
                                                const float* __restrict__ feat2) {
    __shared__ double sred[256];
    __shared__ double sh_AtA[45];
    __shared__ double sh_F[9];
    int t = threadIdx.x;

    double th = (double)theta[0];
    double c = cos(th), s = sin(th);

    float2 p1l[8], p2l[8];
    double s1x = 0, s1y = 0, s2x = 0, s2y = 0;
#pragma unroll
    for (int k = 0; k < 8; k++) {
        int idx = t + (k << 8);
        const float* f1p = feat1 + (size_t)idx * 130;
        const float* f2p = feat2 + (size_t)idx * 130;
        // pts1 = int32(my_tf_kp)   (values in [0,640) -> trunc == floor)
        float p1x = truncf(f2p[0]);
        float p1y = truncf(f2p[1]);
        // pts2: rotate my_kp about image center, round (RNE), back-transform
        double ax = (double)f1p[0] - 320.0;
        double ay = 240.0 - (double)f1p[1];
        double calx = rint(c * ax - s * ay);
        double caly = rint(s * ax + c * ay);
        float p2x = (float)trunc(calx + 320.0);   // integer-valued; trunc exact
        float p2y = (float)trunc(240.0 - caly);
        p1l[k] = make_float2(p1x, p1y);
        p2l[k] = make_float2(p2x, p2y);
        g_p1[idx] = p1l[k];
        g_p2[idx] = p2l[k];
        s1x += p1x; s1y += p1y; s2x += p2x; s2y += p2y;
    }
    double m1x = block_reduce_sum(s1x, sred) * (1.0 / 2048.0);
    double m1y = block_reduce_sum(s1y, sred) * (1.0 / 2048.0);
    double m2x = block_reduce_sum(s2x, sred) * (1.0 / 2048.0);
    double m2y = block_reduce_sum(s2y, sred) * (1.0 / 2048.0);

    double a1 = 0, a2 = 0;
#pragma unroll
    for (int k = 0; k < 8; k++) {
        double dx = (double)p1l[k].x - m1x, dy = (double)p1l[k].y - m1y;
        a1 += sqrt(dx * dx + dy * dy);
        double ex = (double)p2l[k].x - m2x, ey = (double)p2l[k].y - m2y;
        a2 += sqrt(ex * ex + ey * ey);
    }
    double d1 = block_reduce_sum(a1, sred) * (1.0 / 2048.0);
    double d2 = block_reduce_sum(a2, sred) * (1.0 / 2048.0);
    double sc1 = sqrt(2.0) / d1;
    double sc2 = sqrt(2.0) / d2;

    // accumulate AtA (9x9 symmetric, 45 uniques) in double
    double m[45];
#pragma unroll
    for (int e = 0; e < 45; e++) m[e] = 0.0;
#pragma unroll
    for (int k = 0; k < 8; k++) {
        double u1 = ((double)p1l[k].x - m1x) * sc1;
        double v1 = ((double)p1l[k].y - m1y) * sc1;
        double u2 = ((double)p2l[k].x - m2x) * sc2;
        double v2 = ((double)p2l[k].y - m2y) * sc2;
        double a[9] = {u2 * u1, u2 * v1, u2, v2 * u1, v2 * v1, v2, u1, v1, 1.0};
        int e = 0;
#pragma unroll
        for (int p = 0; p < 9; p++)
#pragma unroll
            for (int q = p; q < 9; q++)
                m[e++] += a[p] * a[q];
    }
    if (t < 45) sh_AtA[t] = 0.0;
    __syncthreads();
    int lane = t & 31;
#pragma unroll
    for (int e = 0; e < 45; e++) {
        double v = m[e];
        for (int o = 16; o; o >>= 1) v += __shfl_down_sync(0xffffffffu, v, o);
        if (lane == 0) atomicAdd(&sh_AtA[e], v);
    }
    __syncthreads();

    if (t == 0) {
        double A[81], V[81];
        {
            int e = 0;
            for (int p = 0; p < 9; p++)
                for (int q = p; q < 9; q++) {
                    A[p * 9 + q] = sh_AtA[e];
                    A[q * 9 + p] = sh_AtA[e];
                    e++;
                }
        }
        jacobi_sym(A, V, 9);
        int mi = 0;
        for (int i = 1; i < 9; i++)
            if (A[i * 9 + i] < A[mi * 9 + mi]) mi = i;
        double F[9];
        for (int i = 0; i < 9; i++) F[i] = V[i * 9 + mi];

        // rank-2 projection: F2 = F - (F v3) v3^T, v3 = min-eigvec of F^T F
        double G[9], V3[9];
        for (int r = 0; r < 3; r++)
            for (int cc = 0; cc < 3; cc++) {
                double acc = 0;
                for (int kk = 0; kk < 3; kk++) acc += F[kk * 3 + r] * F[kk * 3 + cc];
                G[r * 3 + cc] = acc;
            }
        jacobi_sym(G, V3, 3);
        int mi3 = 0;
        for (int i = 1; i < 3; i++)
            if (G[i * 3 + i] < G[mi3 * 3 + mi3]) mi3 = i;
        double v3[3] = {V3[0 * 3 + mi3], V3[1 * 3 + mi3], V3[2 * 3 + mi3]};
        double Fv[3];
        for (int r = 0; r < 3; r++)
            Fv[r] = F[r * 3 + 0] * v3[0] + F[r * 3 + 1] * v3[1] + F[r * 3 + 2] * v3[2];
        double F2[9];
        for (int r = 0; r < 3; r++)
            for (int cc = 0; cc < 3; cc++)
                F2[r * 3 + cc] = F[r * 3 + cc] - Fv[r] * v3[cc];

        // denormalize: M = T2^T F2 T1 ; T = [[s,0,-s*mx],[0,s,-s*my],[0,0,1]]
        double M1[9];  // T2^T * F2
        for (int cc = 0; cc < 3; cc++) {
            M1[0 * 3 + cc] = sc2 * F2[0 * 3 + cc];
            M1[1 * 3 + cc] = sc2 * F2[1 * 3 + cc];
            M1[2 * 3 + cc] = (-sc2 * m2x) * F2[0 * 3 + cc] +
                             (-sc2 * m2y) * F2[1 * 3 + cc] + F2[2 * 3 + cc];
        }
        double M[9];  // M1 * T1
        for (int r = 0; r < 3; r++) {
            M[r * 3 + 0] = M1[r * 3 + 0] * sc1;
            M[r * 3 + 1] = M1[r * 3 + 1] * sc1;
            M[r * 3 + 2] = M1[r * 3 + 0] * (-sc1 * m1x) +
                           M1[r * 3 + 1] * (-sc1 * m1y) + M1[r * 3 + 2];
        }
        double inv = 1.0 / M[8];
        for (int i = 0; i < 9; i++) sh_F[i] = M[i] * inv;
    }
    __syncthreads();

    // L[i] = p1h[i]^T F   (row i of pts1, homogeneous)
#pragma unroll
    for (int k = 0; k < 8; k++) {
        int idx = t + (k << 8);
        double px = (double)p1l[k].x, py = (double)p1l[k].y;
        double L0 = px * sh_F[0] + py * sh_F[3] + sh_F[6];
        double L1 = px * sh_F[1] + py * sh_F[4] + sh_F[7];
        double L2 = px * sh_F[2] + py * sh_F[5] + sh_F[8];
        g_L[idx] = make_float4((float)L0, (float)L1, (float)L2, 0.0f);
    }
}

// ---------------- K2: C[i][j] = L1(desc1[i],desc2[j]) + |L[i].p2h[j]| -------
__global__ void __launch_bounds__(256) k2_cost(float* __restrict__ C) {
    __shared__ float As[8][128];
    __shared__ float Bs[8][128];
    int t = threadIdx.x;
    int bi = blockIdx.y << 7;
    int bj = blockIdx.x << 7;
    int tx = t & 15, ty = t >> 4;
    int lr = t & 127, lh = (t >> 7) << 2;  // 0 or 4

    float acc[8][8];
#pragma unroll
    for (int mm = 0; mm < 8; mm++)
#pragma unroll
        for (int nn = 0; nn < 8; nn++) acc[mm][nn] = 0.0f;

    const float4* A4 = (const float4*)(g_d1 + (size_t)(bi + lr) * 128);
    const float4* B4 = (const float4*)(g_d2 + (size_t)(bj + lr) * 128);

    for (int k0 = 0; k0 < 128; k0 += 8) {
        float4 av = A4[(k0 + lh) >> 2];
        float4 bv = B4[(k0 + lh) >> 2];
        As[lh + 0][lr] = av.x; As[lh + 1][lr] = av.y;
        As[lh + 2][lr] = av.z; As[lh + 3][lr] = av.w;
        Bs[lh + 0][lr] = bv.x; Bs[lh + 1][lr] = bv.y;
        Bs[lh + 2][lr] = bv.z; Bs[lh + 3][lr] = bv.w;
        __syncthreads();
#pragma unroll
        for (int kk = 0; kk < 8; kk++) {
            float a[8], b[8];
            *(float4*)&a[0] = *(const float4*)&As[kk][ty << 3];
            *(float4*)&a[4] = *(const float4*)&As[kk][(ty << 3) + 4];
            *(float4*)&b[0] = *(const float4*)&Bs[kk][tx << 3];
            *(float4*)&b[4] = *(const float4*)&Bs[kk][(tx << 3) + 4];
#pragma unroll
            for (int mm = 0; mm < 8; mm++)
#pragma unroll
                for (int nn = 0; nn < 8; nn++)
                    acc[mm][nn] += fabsf(a[mm] - b[nn]);
        }
        __syncthreads();
    }

    // kp epilogue
    float4 Lm[8];
    float2 Pn[8];
#pragma unroll
    for (int mm = 0; mm < 8; mm++) Lm[mm] = g_L[bi + (ty << 3) + mm];
#pragma unroll
    for (int nn = 0; nn < 8; nn++) Pn[nn] = g_p2[bj + (tx << 3) + nn];
#pragma unroll
    for (int mm = 0; mm < 8; mm++)
#pragma unroll
        for (int nn = 0; nn < 8; nn++)
            acc[mm][nn] += fabsf(Lm[mm].x * Pn[nn].x + Lm[mm].y * Pn[nn].y + Lm[mm].z);

#pragma unroll
    for (int mm = 0; mm < 8; mm++) {
        float* dst = C + (size_t)(bi + (ty << 3) + mm) * 2048 + bj + (tx << 3);
        ((float4*)dst)[0] = make_float4(acc[mm][0], acc[mm][1], acc[mm][2], acc[mm][3]);
        ((float4*)dst)[1] = make_float4(acc[mm][4], acc[mm][5], acc[mm][6], acc[mm][7]);
    }
}

// ---------------- K3: JV shortest-augmenting-path per batch ----------------
__global__ void __launch_bounds__(256) k3_hungarian(const float* __restrict__ C,
                                                    float* __restrict__ out_matches) {
    __shared__ double sh_shortest[NB];
    __shared__ double sh_v[NB], sh_u[NB];
    __shared__ int sh_path[NB], sh_row4col[NB], sh_col4row[NB];
    __shared__ unsigned char sh_remaining[NB], sh_inSR[NB];
    __shared__ double red_val[8];
    __shared__ int red_idx[8];
    __shared__ int sh_i, sh_sink;
    __shared__ double sh_minval;

    int j = threadIdx.x;
    int b = blockIdx.x;
    const float* Cb = C + (size_t)(b * NB) * 2048 + b * NB;

    sh_v[j] = 0.0; sh_u[j] = 0.0;
    sh_row4col[j] = -1; sh_col4row[j] = -1;
    __syncthreads();

    int lane = j & 31, warp = j >> 5;

    for (int cur = 0; cur < NB; cur++) {
        sh_shortest[j] = 1e300;
        sh_remaining[j] = 1;
        sh_inSR[j] = 0;
        if (j == 0) { sh_i = cur; sh_minval = 0.0; sh_sink = -1; }
        __syncthreads();

        while (true) {
            int i = sh_i;
            double minval = sh_minval;
            if (j == 0) sh_inSR[i] = 1;
            double ui = sh_u[i];
            double val = 1e301;
            if (sh_remaining[j]) {
                double r = minval + (double)Cb[(size_t)i * 2048 + j] - ui - sh_v[j];
                if (r < sh_shortest[j]) { sh_shortest[j] = r; sh_path[j] = i; }
                val = sh_shortest[j];
            }
            // block argmin, lowest index on ties (matches np.argmin)
            double bv = val; int bi = j;
#pragma unroll
            for (int o = 16; o; o >>= 1) {
                double ov = __shfl_down_sync(0xffffffffu, bv, o);
                int oi = __shfl_down_sync(0xffffffffu, bi, o);
                if (ov < bv || (ov == bv && oi < bi)) { bv = ov; bi = oi; }
            }
            if (lane == 0) { red_val[warp] = bv; red_idx[warp] = bi; }
            __syncthreads();
            if (j == 0) {
                bv = red_val[0]; bi = red_idx[0];
                for (int w = 1; w < 8; w++) {
                    if (red_val[w] < bv || (red_val[w] == bv && red_idx[w] < bi)) {
                        bv = red_val[w]; bi = red_idx[w];
                    }
                }
                sh_minval = bv;
                sh_remaining[bi] = 0;
                int r4c = sh_row4col[bi];
                if (r4c < 0) sh_sink = bi; else sh_i = r4c;
            }
            __syncthreads();
            if (sh_sink >= 0) break;
        }

        double minval = sh_minval;
        int sink = sh_sink;
        double newu = sh_u[j];
        if (sh_inSR[j]) {
            if (j == cur) newu += minval;
            else newu += minval - sh_shortest[sh_col4row[j]];
        }
        double newv = sh_v[j];
        if (!sh_remaining[j]) newv -= minval - sh_shortest[j];
        __syncthreads();
        sh_u[j] = newu;
        sh_v[j] = newv;
        __syncthreads();
        if (j == 0) {
            int jj = sink;
            while (true) {
                int i2 = sh_path[jj];
                sh_row4col[jj] = i2;
                int tmp = sh_col4row[i2];
                sh_col4row[i2] = jj;
                jj = tmp;
                if (i2 == cur) break;
            }
        }
        __syncthreads();
    }

    // matches[b] = stack([arange(N), col4row]) -> shape (B, 2, N)
    out_matches[b * 512 + j]       = (float)j;
    out_matches[b * 512 + 256 + j] = (float)sh_col4row[j];
}

// ---------------- launch ----------------------------------------------------
extern "C" void kernel_launch(void* const* d_in, const int* in_sizes, int n_in,
                              void* d_out, int out_size) {
    const float* theta = (const float*)d_in[0];
    const float* feat1 = (const float*)d_in[1];  // my_feature
    const float* feat2 = (const float*)d_in[2];  // my_tf_feature
    float* C = (float*)d_out;
    float* matches = C + (size_t)2048 * 2048;

    k0_repack<<<(BN_TOTAL * NDESC + 255) / 256, 256>>>(feat1, feat2);
    k1_model<<<1, 256>>>(theta, feat1, feat2);
    k2_cost<<<dim3(16, 16), 256>>>(C);
    k3_hungarian<<<8, 256>>>(C, matches);
}